// round 8
// baseline (speedup 1.0000x reference)
#include <cuda_runtime.h>
#include <cstdint>

// inputs: (B=8, H=160, W=160, C=256) fp32 NHWC
// rois:   (N=1024, 5) fp32 [img_id, x0, y0, x1, y1]
// im_info:(N, 2) fp32 [H_img, W_img]
// output: (N, 7, 7, 256) fp32 = crop_and_resize(14x14 bilinear) -> maxpool 2x2 s2
//
// R8: R5 structure (row-blocks, image-binned order, R5 lerp) + warp-uniform
// tap DEDUP: the 16 taps form a 4x4 grid of (row, col) cells; duplicate
// rows/cols (avg unique ~3.4 each) become predicated-off loads + reg copies.

#define FEAT_H 160
#define FEAT_W 160
#define FEAT_C 256
#define CROP   14
#define POOL   7
#define C4     (FEAT_C / 4)   // 64 float4 per spatial cell
#define NBATCH 8
#define MAXROI 4096

__device__ int g_order[MAXROI];

// ---- single-block binning kernel: sort roi indices by image id ----
__global__ void bin_rois_kernel(const float* __restrict__ rois, int n)
{
    __shared__ int s_cnt[NBATCH];
    __shared__ int s_cur[NBATCH];
    const int t = threadIdx.x;

    if (t < NBATCH) s_cnt[t] = 0;
    __syncthreads();

    int bin = -1;
    if (t < n) {
        bin = (int)rois[t * 5 + 0];
        bin = min(max(bin, 0), NBATCH - 1);
        atomicAdd(&s_cnt[bin], 1);
    }
    __syncthreads();

    if (t == 0) {
        int acc = 0;
        #pragma unroll
        for (int i = 0; i < NBATCH; ++i) { s_cur[i] = acc; acc += s_cnt[i]; }
    }
    __syncthreads();

    if (t < n) {
        int pos = atomicAdd(&s_cur[bin], 1);
        g_order[pos] = t;
    }
}

__device__ __forceinline__ void stcs_f4(float4* p, float4 v) {
    asm volatile("st.global.cs.v4.f32 [%0], {%1, %2, %3, %4};"
                 :: "l"(p), "f"(v.x), "f"(v.y), "f"(v.z), "f"(v.w) : "memory");
}

// R5-exact bilinear + mask + running max for one tap-quad
#define QUADMAX(tl, tr, bl, br, xw, yw, ok, vmax) do {                         \
    float top, bot, r;                                                         \
    top = (tl).x + ((tr).x - (tl).x) * (xw);                                   \
    bot = (bl).x + ((br).x - (bl).x) * (xw);                                   \
    r = top + (bot - top) * (yw); if (!(ok)) r = 0.0f;                         \
    (vmax).x = fmaxf((vmax).x, r);                                             \
    top = (tl).y + ((tr).y - (tl).y) * (xw);                                   \
    bot = (bl).y + ((br).y - (bl).y) * (xw);                                   \
    r = top + (bot - top) * (yw); if (!(ok)) r = 0.0f;                         \
    (vmax).y = fmaxf((vmax).y, r);                                             \
    top = (tl).z + ((tr).z - (tl).z) * (xw);                                   \
    bot = (bl).z + ((br).z - (bl).z) * (xw);                                   \
    r = top + (bot - top) * (yw); if (!(ok)) r = 0.0f;                         \
    (vmax).z = fmaxf((vmax).z, r);                                             \
    top = (tl).w + ((tr).w - (tl).w) * (xw);                                   \
    bot = (bl).w + ((br).w - (bl).w) * (xw);                                   \
    r = top + (bot - top) * (yw); if (!(ok)) r = 0.0f;                         \
    (vmax).w = fmaxf((vmax).w, r);                                             \
} while (0)

__global__ __launch_bounds__(128)
void roipool_kernel(const float* __restrict__ in,
                    const float* __restrict__ rois,
                    const float* __restrict__ im_info,
                    float* __restrict__ out)
{
    const int blk  = blockIdx.x;          // sorted_roi * 7 + py
    const int sroi = blk / POOL;
    const int py   = blk - sroi * POOL;
    const int roi  = g_order[sroi];       // image-binned roi index (broadcast)
    const int t    = threadIdx.x;
    const int slot = t >> 6;              // 0 or 1 (warp-pair granular)
    const int lane = t & 63;              // float4 channel lane

    // --- ROI parameters (warp-uniform broadcast loads) ---
    const float b_f   = __ldg(&rois[roi * 5 + 0]);
    const float H_img = __ldg(&im_info[roi * 2 + 0]);
    const float W_img = __ldg(&im_info[roi * 2 + 1]);
    const float x1 = __ldg(&rois[roi * 5 + 1]) / W_img;
    const float y1 = __ldg(&rois[roi * 5 + 2]) / H_img;
    const float x2 = __ldg(&rois[roi * 5 + 3]) / W_img;
    const float y2 = __ldg(&rois[roi * 5 + 4]) / H_img;
    const int   b  = (int)b_f;

    // Reference arithmetic: y1*(Hf-1) + iy * ((y2-y1)*(Hf-1)/(ch-1))
    const float Hm1 = (float)(FEAT_H - 1);
    const float Wm1 = (float)(FEAT_W - 1);
    const float sy = (y2 - y1) * Hm1 / (float)(CROP - 1);
    const float sx = (x2 - x1) * Wm1 / (float)(CROP - 1);
    const float by = y1 * Hm1;
    const float bx = x1 * Wm1;

    // --- the 2 crop-y rows for this pooled row (shared by all 7 pixels) ---
    float ylp[2];
    int   rl[2], rh[2];
    bool  vy[2];
    const int rb0 = b * (FEAT_H * FEAT_W);
    #pragma unroll
    for (int i = 0; i < 2; ++i) {
        const float y = by + (float)(2 * py + i) * sy;
        vy[i]  = (y >= 0.0f) && (y <= Hm1);
        const float yf = floorf(y);
        ylp[i] = y - yf;
        const int yl = min(max((int)yf, 0), FEAT_H - 1);
        const int yh = min(max((int)yf + 1, 0), FEAT_H - 1);
        rl[i] = (rb0 + yl * FEAT_W) * C4;     // float4 row offsets
        rh[i] = (rb0 + yh * FEAT_W) * C4;
    }
    // unique-row analysis (block-uniform)
    const int ra = rl[0], rb = rh[0], rc = rl[1], rd = rh[1];
    const bool r2_is_b = (rc == rb);
    const bool r2_is_a = (rc == ra);
    const bool r2new   = !(r2_is_b || r2_is_a);
    const bool r3_is_c = (rd == rc);
    const bool r3_is_b = (rd == rb);
    const bool r3new   = !(r3_is_c || r3_is_b);

    const float4* __restrict__ base = (const float4*)in + lane;
    const float NEG_INF = __int_as_float(0xff800000);

    #pragma unroll
    for (int it = 0; it < 4; ++it) {
        const int px = 2 * it + slot;      // slot1@it3 -> px=7 (skip, warp-granular)
        if (px < POOL) {
            // --- 2 crop-x columns for this pooled pixel ---
            float xlp[2];
            int   cxl[2], cxh[2];
            bool  vx[2];
            #pragma unroll
            for (int i = 0; i < 2; ++i) {
                const float x = bx + (float)(2 * px + i) * sx;
                vx[i]  = (x >= 0.0f) && (x <= Wm1);
                const float xf = floorf(x);
                xlp[i] = x - xf;
                cxl[i] = min(max((int)xf, 0), FEAT_W - 1) * C4;
                cxh[i] = min(max((int)xf + 1, 0), FEAT_W - 1) * C4;
            }
            // unique-col analysis (warp-uniform for this pixel slot)
            const int ca = cxl[0], cb = cxh[0], cc = cxl[1], cd = cxh[1];
            const bool c2_is_b = (cc == cb);
            const bool c2_is_a = (cc == ca);
            const bool c2new   = !(c2_is_b || c2_is_a);
            const bool c3_is_c = (cd == cc);
            const bool c3_is_b = (cd == cb);
            const bool c3new   = !(c3_is_c || c3_is_b);

            // --- 4x4 cell grid with deduped loads (predicated LDG + copies) ---
            float4 v00, v01, v02, v03;
            float4 v10, v11, v12, v13;
            float4 v20, v21, v22, v23;
            float4 v30, v31, v32, v33;

            // row ra (always loaded)
            v00 = __ldg(base + (ra + ca));
            v01 = __ldg(base + (ra + cb));
            v02 = c2new ? __ldg(base + (ra + cc)) : (c2_is_b ? v01 : v00);
            v03 = c3new ? __ldg(base + (ra + cd)) : (c3_is_c ? v02 : v01);
            // row rb (always loaded)
            v10 = __ldg(base + (rb + ca));
            v11 = __ldg(base + (rb + cb));
            v12 = c2new ? __ldg(base + (rb + cc)) : (c2_is_b ? v11 : v10);
            v13 = c3new ? __ldg(base + (rb + cd)) : (c3_is_c ? v12 : v11);
            // row rc
            if (r2new) {
                v20 = __ldg(base + (rc + ca));
                v21 = __ldg(base + (rc + cb));
                v22 = c2new ? __ldg(base + (rc + cc)) : (c2_is_b ? v21 : v20);
                v23 = c3new ? __ldg(base + (rc + cd)) : (c3_is_c ? v22 : v21);
            } else if (r2_is_b) {
                v20 = v10; v21 = v11; v22 = v12; v23 = v13;
            } else {
                v20 = v00; v21 = v01; v22 = v02; v23 = v03;
            }
            // row rd
            if (r3new) {
                v30 = __ldg(base + (rd + ca));
                v31 = __ldg(base + (rd + cb));
                v32 = c2new ? __ldg(base + (rd + cc)) : (c2_is_b ? v31 : v30);
                v33 = c3new ? __ldg(base + (rd + cd)) : (c3_is_c ? v32 : v31);
            } else if (r3_is_c) {
                v30 = v20; v31 = v21; v32 = v22; v33 = v23;
            } else {
                v30 = v10; v31 = v11; v32 = v12; v33 = v13;
            }

            // --- bilinear + mask + running max (single path, R5 formula) ---
            float4 vmax = make_float4(NEG_INF, NEG_INF, NEG_INF, NEG_INF);
            const bool ok00 = vy[0] && vx[0];
            const bool ok01 = vy[0] && vx[1];
            const bool ok10 = vy[1] && vx[0];
            const bool ok11 = vy[1] && vx[1];
            QUADMAX(v00, v01, v10, v11, xlp[0], ylp[0], ok00, vmax);
            QUADMAX(v02, v03, v12, v13, xlp[1], ylp[0], ok01, vmax);
            QUADMAX(v20, v21, v30, v31, xlp[0], ylp[1], ok10, vmax);
            QUADMAX(v22, v23, v32, v33, xlp[1], ylp[1], ok11, vmax);

            // output goes to the ORIGINAL roi slot; streaming store (never re-read)
            stcs_f4((float4*)out + ((roi * 49 + py * POOL + px) * C4 + lane), vmax);
        }
    }
}

extern "C" void kernel_launch(void* const* d_in, const int* in_sizes, int n_in,
                              void* d_out, int out_size)
{
    const float* in      = (const float*)d_in[0];
    const float* rois    = (const float*)d_in[1];
    const float* im_info = (const float*)d_in[2];
    float* out           = (float*)d_out;

    const int N = in_sizes[1] / 5;   // 1024
    bin_rois_kernel<<<1, 1024>>>(rois, N);
    roipool_kernel<<<N * POOL, 128>>>(in, rois, im_info, out);
}

// round 9
// speedup vs baseline: 1.2883x; 1.2883x over previous
#include <cuda_runtime.h>
#include <cstdint>

// inputs: (B=8, H=160, W=160, C=256) fp32 NHWC
// rois:   (N=1024, 5) fp32 [img_id, x0, y0, x1, y1]
// im_info:(N, 2) fp32 [H_img, W_img]
// output: (N, 7, 7, 256) fp32 = crop_and_resize(14x14 bilinear) -> maxpool 2x2 s2
//
// R9: exact R5 winner (row-blocks + image-binned order + batched 16xLDG.128)
// with __launch_bounds__(128, 10) to cap regs ~51 and lift occupancy to
// 10 blocks/SM (40 warps, 62.5%) for better latency hiding.

#define FEAT_H 160
#define FEAT_W 160
#define FEAT_C 256
#define CROP   14
#define POOL   7
#define C4     (FEAT_C / 4)   // 64 float4 per spatial cell
#define NBATCH 8
#define MAXROI 4096

__device__ int g_order[MAXROI];

// ---- single-block binning kernel: sort roi indices by image id ----
__global__ void bin_rois_kernel(const float* __restrict__ rois, int n)
{
    __shared__ int s_cnt[NBATCH];
    __shared__ int s_cur[NBATCH];
    const int t = threadIdx.x;

    if (t < NBATCH) s_cnt[t] = 0;
    __syncthreads();

    int bin = -1;
    if (t < n) {
        bin = (int)rois[t * 5 + 0];
        bin = min(max(bin, 0), NBATCH - 1);
        atomicAdd(&s_cnt[bin], 1);
    }
    __syncthreads();

    if (t == 0) {
        int acc = 0;
        #pragma unroll
        for (int i = 0; i < NBATCH; ++i) { s_cur[i] = acc; acc += s_cnt[i]; }
    }
    __syncthreads();

    if (t < n) {
        int pos = atomicAdd(&s_cur[bin], 1);
        g_order[pos] = t;
    }
}

__device__ __forceinline__ void stcs_f4(float4* p, float4 v) {
    asm volatile("st.global.cs.v4.f32 [%0], {%1, %2, %3, %4};"
                 :: "l"(p), "f"(v.x), "f"(v.y), "f"(v.z), "f"(v.w) : "memory");
}

__global__ __launch_bounds__(128, 10)
void roipool_kernel(const float* __restrict__ in,
                    const float* __restrict__ rois,
                    const float* __restrict__ im_info,
                    float* __restrict__ out)
{
    const int blk  = blockIdx.x;          // sorted_roi * 7 + py
    const int sroi = blk / POOL;
    const int py   = blk - sroi * POOL;
    const int roi  = g_order[sroi];       // image-binned roi index (broadcast)
    const int t    = threadIdx.x;
    const int slot = t >> 6;              // 0 or 1 (warp-pair granular)
    const int lane = t & 63;              // float4 channel lane

    // --- ROI parameters (warp-uniform broadcast loads) ---
    const float b_f   = __ldg(&rois[roi * 5 + 0]);
    const float H_img = __ldg(&im_info[roi * 2 + 0]);
    const float W_img = __ldg(&im_info[roi * 2 + 1]);
    const float x1 = __ldg(&rois[roi * 5 + 1]) / W_img;
    const float y1 = __ldg(&rois[roi * 5 + 2]) / H_img;
    const float x2 = __ldg(&rois[roi * 5 + 3]) / W_img;
    const float y2 = __ldg(&rois[roi * 5 + 4]) / H_img;
    const int   b  = (int)b_f;

    // Reference arithmetic: y1*(Hf-1) + iy * ((y2-y1)*(Hf-1)/(ch-1))
    const float Hm1 = (float)(FEAT_H - 1);
    const float Wm1 = (float)(FEAT_W - 1);
    const float sy = (y2 - y1) * Hm1 / (float)(CROP - 1);
    const float sx = (x2 - x1) * Wm1 / (float)(CROP - 1);
    const float by = y1 * Hm1;
    const float bx = x1 * Wm1;

    // --- the 2 crop-y rows for this pooled row (shared by all 7 pixels) ---
    float ylp[2];
    int   rl[2], rh[2];
    bool  vy[2];
    const int rb = b * (FEAT_H * FEAT_W);
    #pragma unroll
    for (int i = 0; i < 2; ++i) {
        const float y = by + (float)(2 * py + i) * sy;
        vy[i]  = (y >= 0.0f) && (y <= Hm1);
        const float yf = floorf(y);
        ylp[i] = y - yf;
        const int yl = min(max((int)yf, 0), FEAT_H - 1);
        const int yh = min(max((int)yf + 1, 0), FEAT_H - 1);
        rl[i] = (rb + yl * FEAT_W) * C4;     // float4 row offsets
        rh[i] = (rb + yh * FEAT_W) * C4;
    }

    const float4* __restrict__ base = (const float4*)in + lane;
    const float NEG_INF = __int_as_float(0xff800000);

    #pragma unroll
    for (int it = 0; it < 4; ++it) {
        const int px = 2 * it + slot;      // slot1@it3 -> px=7 (skip, warp-granular)
        if (px < POOL) {
            // --- 2 crop-x columns for this pooled pixel ---
            float xlp[2];
            int   cxl[2], cxh[2];
            bool  vx[2];
            #pragma unroll
            for (int i = 0; i < 2; ++i) {
                const float x = bx + (float)(2 * px + i) * sx;
                vx[i]  = (x >= 0.0f) && (x <= Wm1);
                const float xf = floorf(x);
                xlp[i] = x - xf;
                cxl[i] = min(max((int)xf, 0), FEAT_W - 1) * C4;
                cxh[i] = min(max((int)xf + 1, 0), FEAT_W - 1) * C4;
            }

            // --- all 16 taps batched (LDG.128), one latency exposure ---
            float4 v[16];
            #pragma unroll
            for (int iy = 0; iy < 2; ++iy) {
                #pragma unroll
                for (int ix = 0; ix < 2; ++ix) {
                    const int k = (iy * 2 + ix) * 4;
                    v[k + 0] = __ldg(base + (rl[iy] + cxl[ix]));  // tl
                    v[k + 1] = __ldg(base + (rl[iy] + cxh[ix]));  // tr
                    v[k + 2] = __ldg(base + (rh[iy] + cxl[ix]));  // bl
                    v[k + 3] = __ldg(base + (rh[iy] + cxh[ix]));  // br
                }
            }

            // --- bilinear + mask + running max ---
            float4 vmax = make_float4(NEG_INF, NEG_INF, NEG_INF, NEG_INF);
            #pragma unroll
            for (int iy = 0; iy < 2; ++iy) {
                #pragma unroll
                for (int ix = 0; ix < 2; ++ix) {
                    const int k = (iy * 2 + ix) * 4;
                    const float yw = ylp[iy];
                    const float xw = xlp[ix];
                    const bool  ok = vy[iy] && vx[ix];
                    const float4 tl = v[k + 0], tr = v[k + 1];
                    const float4 bl = v[k + 2], br = v[k + 3];
                    float top, bot, r;
                    float4 rv;
                    top = tl.x + (tr.x - tl.x) * xw; bot = bl.x + (br.x - bl.x) * xw; r = top + (bot - top) * yw; rv.x = r;
                    top = tl.y + (tr.y - tl.y) * xw; bot = bl.y + (br.y - bl.y) * xw; r = top + (bot - top) * yw; rv.y = r;
                    top = tl.z + (tr.z - tl.z) * xw; bot = bl.z + (br.z - bl.z) * xw; r = top + (bot - top) * yw; rv.z = r;
                    top = tl.w + (tr.w - tl.w) * xw; bot = bl.w + (br.w - bl.w) * xw; r = top + (bot - top) * yw; rv.w = r;
                    if (!ok) rv = make_float4(0.0f, 0.0f, 0.0f, 0.0f);
                    vmax.x = fmaxf(vmax.x, rv.x);
                    vmax.y = fmaxf(vmax.y, rv.y);
                    vmax.z = fmaxf(vmax.z, rv.z);
                    vmax.w = fmaxf(vmax.w, rv.w);
                }
            }

            // output goes to the ORIGINAL roi slot; streaming store (never re-read)
            stcs_f4((float4*)out + ((roi * 49 + py * POOL + px) * C4 + lane), vmax);
        }
    }
}

extern "C" void kernel_launch(void* const* d_in, const int* in_sizes, int n_in,
                              void* d_out, int out_size)
{
    const float* in      = (const float*)d_in[0];
    const float* rois    = (const float*)d_in[1];
    const float* im_info = (const float*)d_in[2];
    float* out           = (float*)d_out;

    const int N = in_sizes[1] / 5;   // 1024
    bin_rois_kernel<<<1, 1024>>>(rois, N);
    roipool_kernel<<<N * POOL, 128>>>(in, rois, im_info, out);
}